// round 3
// baseline (speedup 1.0000x reference)
#include <cuda_runtime.h>
#include <cuda_fp16.h>

// Problem constants (fixed by dataset)
#define NB    16
#define INCC  32
#define INNX  65536
#define OUTCC 32
#define OUTNX 8192
#define MAXD  16
#define NF    512     // NB*INCC feature columns

// 64 MB fp16 feature table: feat[inn][j] = x[n,c,inn]*weight[c,inn], j = n*32+c
__device__ __half g_feat_h[(size_t)INNX * NF];
// 16 MB pooled intermediate, stored in a lane-permuted float4 layout (see below)
__device__ float g_pooled[(size_t)OUTNX * NF];

// ---------------------------------------------------------------------------
// Kernel 1: fused scale + transpose + fp32->fp16.
// Tile = 64 j x 32 inn. 8 strided scalar loads per thread (MLP=8), smem
// [64][33] fp32 (2-way conflicts on transposed read only), 128B coalesced
// half2 row stores. x read with __ldcs to keep L2 free for the table.
// ---------------------------------------------------------------------------
__global__ __launch_bounds__(256) void prep_kernel(const float* __restrict__ x,
                                                   const float* __restrict__ w) {
    __shared__ float tile[64][33];
    const int inn0 = blockIdx.x << 5;
    const int j0   = blockIdx.y << 6;
    const int tx = threadIdx.x, ty = threadIdx.y;   // 32 x 8
    const int inn = inn0 + tx;

#pragma unroll
    for (int r = 0; r < 8; r++) {
        const int jl = ty + (r << 3);
        const int j  = j0 + jl;
        const int c  = j & 31;
        tile[jl][tx] = __ldcs(x + (size_t)j * INNX + inn) * __ldg(w + (size_t)c * INNX + inn);
    }
    __syncthreads();

    __half2* out2 = (__half2*)g_feat_h;   // row stride = 256 half2
    const int tid = (ty << 5) + tx;
#pragma unroll
    for (int k = 0; k < 4; k++) {
        const int e     = tid + (k << 8);
        const int inn_l = e >> 5;          // 0..31
        const int l     = e & 31;          // half2 col within tile
        const float a = tile[2 * l][inn_l];
        const float b = tile[2 * l + 1][inn_l];
        out2[(size_t)(inn0 + inn_l) * 256 + (j0 >> 1) + l] = __floats2half2_rn(a, b);
    }
}

// ---------------------------------------------------------------------------
// Kernel 2: gather + weighted pool only. Warp-per-output-node, no smem work,
// no CTA syncs, low regs -> high occupancy. Writes pooled as float4 in a
// permuted layout so every store instruction is fully contiguous:
//   block b in {0..3}: p4[o*128 + b*32 + lane]
//   b=0: j[8L..8L+4)        b=1: j[8L+4..8L+8)
//   b=2: j[256+8L..+4)      b=3: j[256+8L+4..+8)    (L = lane)
// ---------------------------------------------------------------------------
__global__ __launch_bounds__(256) void gather_kernel(
    const void*  __restrict__ Araw,
    const float* __restrict__ mask,
    const float* __restrict__ mw)
{
    __shared__ int s_is64;
    const int tid  = threadIdx.x;
    const int w    = tid >> 5;
    const int lane = tid & 31;

    if (tid == 0) {
        const long long* a64 = (const long long*)Araw;
        int is64 = 1;
#pragma unroll
        for (int i = 0; i < 8; i++)
            if ((unsigned long long)a64[i] >= (unsigned long long)INNX) is64 = 0;
        s_is64 = is64;
    }
    __syncthreads();
    const int is64 = s_is64;

    const int o = blockIdx.x * 8 + w;

    int   av = 0;
    float wv = 0.f;
    if (lane < MAXD) {
        av = is64 ? (int)((const long long*)Araw)[(size_t)o * MAXD + lane]
                  : ((const int*)Araw)[(size_t)o * MAXD + lane];
        wv = mw[o * MAXD + lane] * mask[o * MAXD + lane];
    }

    const uint4* feat4 = (const uint4*)g_feat_h;   // row stride = 64 uint4
    float acc[16];
#pragma unroll
    for (int i = 0; i < 16; i++) acc[i] = 0.f;

#pragma unroll
    for (int d = 0; d < MAXD; d++) {
        const int   idx = __shfl_sync(0xffffffffu, av, d);
        const float wd  = __shfl_sync(0xffffffffu, wv, d);
        const uint4* row = feat4 + (size_t)idx * 64;
        uint4 u0 = row[lane];
        uint4 u1 = row[lane + 32];
        const __half2* h0 = (const __half2*)&u0;
        const __half2* h1 = (const __half2*)&u1;
#pragma unroll
        for (int q = 0; q < 4; q++) {
            float2 f0 = __half22float2(h0[q]);
            float2 f1 = __half22float2(h1[q]);
            acc[2 * q + 0]     += wd * f0.x;
            acc[2 * q + 1]     += wd * f0.y;
            acc[8 + 2 * q + 0] += wd * f1.x;
            acc[8 + 2 * q + 1] += wd * f1.y;
        }
    }

    float4* p4 = (float4*)g_pooled + (size_t)o * 128;
    p4[lane]      = make_float4(acc[0],  acc[1],  acc[2],  acc[3]);
    p4[32 + lane] = make_float4(acc[4],  acc[5],  acc[6],  acc[7]);
    p4[64 + lane] = make_float4(acc[8],  acc[9],  acc[10], acc[11]);
    p4[96 + lane] = make_float4(acc[12], acc[13], acc[14], acc[15]);
}

// ---------------------------------------------------------------------------
// Kernel 3: GEMM + bias + transposed store. 512 threads = 16 warps = 16 o.
// Warp-per-o; ct_weight row in regs (lane = dout); pooled read via uniform
// warp-broadcast LDG.128 (L1/L2 hit); staged smem for 64B-coalesced output.
// ---------------------------------------------------------------------------
__global__ __launch_bounds__(512) void finish_kernel(
    const float* __restrict__ ctw,
    const float* __restrict__ ctb,
    const float* __restrict__ bias,
    float* __restrict__ out)
{
    __shared__ float s_stage[NF][17];
    const int tid  = threadIdx.x;
    const int w    = tid >> 5;
    const int lane = tid & 31;

    float wreg[32];
    {
        const float4* cw4 = (const float4*)(ctw + lane * INCC);
#pragma unroll
        for (int q = 0; q < 8; q++) {
            float4 v = __ldg(cw4 + q);
            wreg[4 * q + 0] = v.x; wreg[4 * q + 1] = v.y;
            wreg[4 * q + 2] = v.z; wreg[4 * q + 3] = v.w;
        }
    }
    const float cb = __ldg(ctb + lane);

    const int o_base = blockIdx.x * 16;
    const int o      = o_base + w;
    const float4* p4 = (const float4*)g_pooled + (size_t)o * 128;

#pragma unroll
    for (int t = 0; t < NB; t++) {
        float y = cb;
#pragma unroll
        for (int c4 = 0; c4 < 8; c4++) {
            // invert the permuted pooled layout: j = t*32 + 4*c4
            const int tl  = t & 7;                 // within 256-half block
            const int blk = (t >> 3) * 2 + (c4 & 1) + 0; // b index pieces
            const int idx = ((t >> 3) ? 64 : 0) + ((c4 & 1) ? 32 : 0) + 4 * tl + (c4 >> 1);
            (void)blk;
            float4 p = __ldg(p4 + idx);            // uniform across warp
            y += p.x * wreg[4 * c4 + 0] + p.y * wreg[4 * c4 + 1]
               + p.z * wreg[4 * c4 + 2] + p.w * wreg[4 * c4 + 3];
        }
        s_stage[t * 32 + lane][w] = y;
    }
    __syncthreads();

#pragma unroll
    for (int e = tid; e < NF * 16; e += 512) {
        const int row  = e >> 4;
        const int col  = e & 15;
        const int oo   = o_base + col;
        const int dout = row & 31;
        out[(size_t)row * OUTNX + oo] = s_stage[row][col] + bias[(size_t)dout * OUTNX + oo];
    }
}

extern "C" void kernel_launch(void* const* d_in, const int* in_sizes, int n_in,
                              void* d_out, int out_size) {
    const float* x    = (const float*)d_in[0];
    const void*  A    = d_in[1];
    const float* w    = (const float*)d_in[2];
    const float* mask = (const float*)d_in[3];
    const float* mw   = (const float*)d_in[4];
    const float* ctw  = (const float*)d_in[5];
    const float* ctb  = (const float*)d_in[6];
    const float* bias = (const float*)d_in[7];
    float* out = (float*)d_out;
    (void)in_sizes; (void)n_in; (void)out_size;

    dim3 pgrid(INNX / 32, NF / 64);
    dim3 pblk(32, 8);
    prep_kernel<<<pgrid, pblk>>>(x, w);

    gather_kernel<<<OUTNX / 8, 256>>>(A, mask, mw);

    finish_kernel<<<OUTNX / 16, 512>>>(ctw, ctb, bias, out);
}

// round 4
// speedup vs baseline: 1.4053x; 1.4053x over previous
#include <cuda_runtime.h>
#include <cuda_fp16.h>

// Problem constants (fixed by dataset)
#define NB    16
#define INCC  32
#define INNX  65536
#define OUTCC 32
#define OUTNX 8192
#define MAXD  16
#define NF    512     // NB*INCC feature columns
#define OB    8       // output nodes per CTA (one per warp)

// 64 MB fp16 feature table: feat[inn][j] = x[n,c,inn]*weight[c,inn], j = n*32+c
__device__ __half g_feat_h[(size_t)INNX * NF];

// ---------------------------------------------------------------------------
// Kernel 1 (unchanged from R3, measured 35.6us): fused scale+transpose+fp16.
// Tile = 64 j x 32 inn, MLP=8 loads/thread, 128B coalesced half2 row stores,
// __ldcs on x to keep L2 free for the feature table.
// ---------------------------------------------------------------------------
__global__ __launch_bounds__(256) void prep_kernel(const float* __restrict__ x,
                                                   const float* __restrict__ w) {
    __shared__ float tile[64][33];
    const int inn0 = blockIdx.x << 5;
    const int j0   = blockIdx.y << 6;
    const int tx = threadIdx.x, ty = threadIdx.y;   // 32 x 8
    const int inn = inn0 + tx;

#pragma unroll
    for (int r = 0; r < 8; r++) {
        const int jl = ty + (r << 3);
        const int j  = j0 + jl;
        const int c  = j & 31;
        tile[jl][tx] = __ldcs(x + (size_t)j * INNX + inn) * __ldg(w + (size_t)c * INNX + inn);
    }
    __syncthreads();

    __half2* out2 = (__half2*)g_feat_h;   // row stride = 256 half2
    const int tid = (ty << 5) + tx;
#pragma unroll
    for (int k = 0; k < 4; k++) {
        const int e     = tid + (k << 8);
        const int inn_l = e >> 5;          // 0..31
        const int l     = e & 31;          // half2 col within tile
        const float a = tile[2 * l][inn_l];
        const float b = tile[2 * l + 1][inn_l];
        out2[(size_t)(inn0 + inn_l) * 256 + (j0 >> 1) + l] = __floats2half2_rn(a, b);
    }
}

// ---------------------------------------------------------------------------
// Kernel 2: FUSED warp-per-output-node gather + pool + register GEMM +
// staged transposed store (R2 design). Register-pressure fix: ct_weight row
// is loaded AFTER the gather phase so its 32-reg footprint doesn't overlap
// the gather accumulators; __launch_bounds__(256,4) caps regs at 64
// -> 4 CTAs/SM (50% occ) instead of 3 (37.5%).
// ---------------------------------------------------------------------------
__global__ __launch_bounds__(256, 4) void gather_kernel(
    const void*  __restrict__ Araw,
    const float* __restrict__ mask,
    const float* __restrict__ mw,
    const float* __restrict__ ctw,
    const float* __restrict__ ctb,
    const float* __restrict__ bias,
    float* __restrict__ out)
{
    __shared__ float s_pool[OB][NF];         // per-warp pooled vector (16 KB)
    __shared__ float s_stage[NF][OB + 1];    // output staging (18 KB)
    __shared__ int   s_is64;

    const int tid  = threadIdx.x;
    const int w    = tid >> 5;
    const int lane = tid & 31;

    if (tid == 0) {
        const long long* a64 = (const long long*)Araw;
        int is64 = 1;
#pragma unroll
        for (int i = 0; i < 8; i++)
            if ((unsigned long long)a64[i] >= (unsigned long long)INNX) is64 = 0;
        s_is64 = is64;
    }
    __syncthreads();
    const int is64 = s_is64;

    const int o_base = blockIdx.x * OB;
    const int o      = o_base + w;

    // neighbor indices + pooling weights, distributed in lanes 0..15
    int   av = 0;
    float wv = 0.f;
    if (lane < MAXD) {
        av = is64 ? (int)((const long long*)Araw)[(size_t)o * MAXD + lane]
                  : ((const int*)Araw)[(size_t)o * MAXD + lane];
        wv = mw[o * MAXD + lane] * mask[o * MAXD + lane];
    }

    // ---- gather + pool: lane handles uint4 cols {lane, lane+32} of 64 ----
    const uint4* feat4 = (const uint4*)g_feat_h;   // row stride = 64 uint4
    float acc[16];
#pragma unroll
    for (int i = 0; i < 16; i++) acc[i] = 0.f;

#pragma unroll
    for (int d = 0; d < MAXD; d++) {
        const int   idx = __shfl_sync(0xffffffffu, av, d);
        const float wd  = __shfl_sync(0xffffffffu, wv, d);
        const uint4* row = feat4 + (size_t)idx * 64;
        uint4 u0 = __ldg(row + lane);
        uint4 u1 = __ldg(row + lane + 32);
        const __half2* h0 = (const __half2*)&u0;
        const __half2* h1 = (const __half2*)&u1;
#pragma unroll
        for (int q = 0; q < 4; q++) {
            float2 f0 = __half22float2(h0[q]);
            float2 f1 = __half22float2(h1[q]);
            acc[2 * q + 0]     += wd * f0.x;
            acc[2 * q + 1]     += wd * f0.y;
            acc[8 + 2 * q + 0] += wd * f1.x;
            acc[8 + 2 * q + 1] += wd * f1.y;
        }
    }

    // pooled -> smem (float4); uint4 col c covers half cols [8c, 8c+8)
    float4* sp4 = (float4*)s_pool[w];
    sp4[lane * 2 + 0]        = make_float4(acc[0],  acc[1],  acc[2],  acc[3]);
    sp4[lane * 2 + 1]        = make_float4(acc[4],  acc[5],  acc[6],  acc[7]);
    sp4[(lane + 32) * 2 + 0] = make_float4(acc[8],  acc[9],  acc[10], acc[11]);
    sp4[(lane + 32) * 2 + 1] = make_float4(acc[12], acc[13], acc[14], acc[15]);
    __syncwarp();

    // ---- load ct_weight row NOW (after acc is dead) to keep reg peak low ----
    float wreg[32];
    {
        const float4* cw4 = (const float4*)(ctw + lane * INCC);
#pragma unroll
        for (int q = 0; q < 8; q++) {
            float4 v = __ldg(cw4 + q);
            wreg[4 * q + 0] = v.x; wreg[4 * q + 1] = v.y;
            wreg[4 * q + 2] = v.z; wreg[4 * q + 3] = v.w;
        }
    }
    const float cb = __ldg(ctb + lane);

    // ---- GEMM: y[n=t][dout=lane] = cb + sum_c pooled[t*32+c]*ctw[lane][c] ----
#pragma unroll
    for (int t = 0; t < NB; t++) {
        float y = cb;
#pragma unroll
        for (int c4 = 0; c4 < 8; c4++) {
            float4 p = sp4[t * 8 + c4];        // warp-broadcast LDS.128
            y += p.x * wreg[4 * c4 + 0] + p.y * wreg[4 * c4 + 1]
               + p.z * wreg[4 * c4 + 2] + p.w * wreg[4 * c4 + 3];
        }
        s_stage[t * 32 + lane][w] = y;
    }
    __syncthreads();

    // ---- coalesced write-out: out[row*8192 + o] = stage + bias ----
#pragma unroll
    for (int e = tid; e < NF * OB; e += 256) {
        const int row  = e >> 3;       // OB == 8
        const int col  = e & 7;
        const int oo   = o_base + col;
        const int dout = row & 31;
        out[(size_t)row * OUTNX + oo] = s_stage[row][col] + __ldg(bias + (size_t)dout * OUTNX + oo);
    }
}

extern "C" void kernel_launch(void* const* d_in, const int* in_sizes, int n_in,
                              void* d_out, int out_size) {
    const float* x    = (const float*)d_in[0];
    const void*  A    = d_in[1];
    const float* w    = (const float*)d_in[2];
    const float* mask = (const float*)d_in[3];
    const float* mw   = (const float*)d_in[4];
    const float* ctw  = (const float*)d_in[5];
    const float* ctb  = (const float*)d_in[6];
    const float* bias = (const float*)d_in[7];
    float* out = (float*)d_out;
    (void)in_sizes; (void)n_in; (void)out_size;

    dim3 pgrid(INNX / 32, NF / 64);
    dim3 pblk(32, 8);
    prep_kernel<<<pgrid, pblk>>>(x, w);

    gather_kernel<<<OUTNX / OB, 256>>>(A, mask, mw, ctw, ctb, bias, out);
}